// round 14
// baseline (speedup 1.0000x reference)
#include <cuda_runtime.h>
#include <mma.h>
using namespace nvcuda;

#define N_NODESC 50000
#define N_EDGESC 800000
#define E2C (N_EDGESC + N_NODESC)
#define D_INC 128
#define D_HIDC 64
#define D_OUTC 32
#define SCAN_BLK 256
#define SCAN_GRID ((N_NODESC + SCAN_BLK - 1) / SCAN_BLK)   // 196
#define W_SPLIT_TOTAL (D_HIDC*D_INC*2 + D_OUTC*D_HIDC*2)   // 20480

// ---------------- scratch (device globals; never referenced from host) --------
// Zero-initialized at module load; gat layer-0 kernel re-zeros the consumed
// counters each call (measured free in R7/R8) so every replay sees zeros.
__device__ __align__(16) int   g_count[N_NODESC];
__device__ __align__(16) float g_attr_sum[N_NODESC];
__device__ __align__(16) float g_loop_attr[N_NODESC];
__device__ __align__(16) int   g_row_ptr[N_NODESC + 1];
__device__ __align__(16) int   g_cursor[N_NODESC];
__device__ __align__(16) int2  g_csr[E2C];                 // (src, attr-bits)
__device__ __align__(16) int   g_bsum[SCAN_GRID];
__device__ __align__(16) int   g_boff[SCAN_GRID];
__device__ __align__(16) float g_whi[W_SPLIT_TOTAL];       // tf32-hi of all 4 W
__device__ __align__(16) float g_wlo[W_SPLIT_TOTAL];       // tf32-lo residuals
__device__ __align__(16) float g_xl [N_NODESC * D_HIDC];
__device__ __align__(16) float g_xr [N_NODESC * D_HIDC];
__device__ __align__(16) float g_h  [N_NODESC * D_HIDC];
__device__ __align__(16) float g_xl2[N_NODESC * D_OUTC];
__device__ __align__(16) float g_xr2[N_NODESC * D_OUTC];

__device__ __forceinline__ const float* lin_in_ptr(const float* xparam, int sel) {
    return (sel == 0) ? xparam : g_h;
}

// ---------------- W hi/lo split (once per call; tiny) ---------------------------
// layout: [0:8192) Wl1, [8192:16384) Wr1, [16384:18432) Wl2, [18432:20480) Wr2
__global__ void wsplit_kernel(const float* __restrict__ Wl1, const float* __restrict__ Wr1,
                              const float* __restrict__ Wl2, const float* __restrict__ Wr2) {
    int i = blockIdx.x * blockDim.x + threadIdx.x;
    if (i >= W_SPLIT_TOTAL) return;
    float v;
    if (i < 8192)       v = Wl1[i];
    else if (i < 16384) v = Wr1[i - 8192];
    else if (i < 18432) v = Wl2[i - 16384];
    else                v = Wr2[i - 18432];
    float hi = wmma::__float_to_tf32(v);
    g_whi[i] = hi;
    g_wlo[i] = wmma::__float_to_tf32(v - hi);
}

// ---------------- preprocessing (R5/R12-proven multi-block structure) -----------
__global__ void count_kernel(const int* __restrict__ ei,
                             const float* __restrict__ ew) {
    int e = blockIdx.x * blockDim.x + threadIdx.x;
    if (e < N_EDGESC) {
        int d = ei[N_EDGESC + e];
        if ((unsigned)d < (unsigned)N_NODESC) {
            atomicAdd(&g_count[d], 1);
            atomicAdd(&g_attr_sum[d], ew[e]);
        }
    }
}

__global__ void scan1_kernel() {   // per-block sums + loop_attr
    __shared__ int red[SCAN_BLK];
    int t = threadIdx.x, b = blockIdx.x;
    int i = b * SCAN_BLK + t;
    int val = 0;
    if (i < N_NODESC) {
        int c = g_count[i];
        val = c + 1;
        g_loop_attr[i] = g_attr_sum[i] / fmaxf((float)c, 1.0f);
    }
    red[t] = val;
    __syncthreads();
#pragma unroll
    for (int off = SCAN_BLK / 2; off > 0; off >>= 1) {
        if (t < off) red[t] += red[t + off];
        __syncthreads();
    }
    if (t == 0) g_bsum[b] = red[0];
}

__global__ void scan2_kernel() {   // exclusive scan of 196 block sums
    __shared__ int sh[SCAN_BLK];
    int t = threadIdx.x;
    int orig = (t < SCAN_GRID) ? g_bsum[t] : 0;
    sh[t] = orig;
    __syncthreads();
    for (int off = 1; off < SCAN_BLK; off <<= 1) {
        int v = (t >= off) ? sh[t - off] : 0;
        __syncthreads();
        sh[t] += v;
        __syncthreads();
    }
    if (t < SCAN_GRID) g_boff[t] = sh[t] - orig;
}

__global__ void scan3_kernel() {   // local scan + block offset -> row_ptr
    __shared__ int sh[SCAN_BLK];
    int t = threadIdx.x, b = blockIdx.x;
    int i = b * SCAN_BLK + t;
    int val = (i < N_NODESC) ? (g_count[i] + 1) : 0;
    sh[t] = val;
    __syncthreads();
    for (int off = 1; off < SCAN_BLK; off <<= 1) {
        int v = (t >= off) ? sh[t - off] : 0;
        __syncthreads();
        sh[t] += v;
        __syncthreads();
    }
    if (i < N_NODESC) g_row_ptr[i] = g_boff[b] + sh[t] - val;
    if (i == N_NODESC) g_row_ptr[N_NODESC] = E2C;
}

__global__ void scatter_kernel(const int* __restrict__ ei,
                               const float* __restrict__ ew) {
    int e = blockIdx.x * blockDim.x + threadIdx.x;
    if (e < N_EDGESC) {
        int d = ei[N_EDGESC + e];
        int s = ei[e];
        if ((unsigned)d < (unsigned)N_NODESC && (unsigned)s < (unsigned)N_NODESC) {
            int pos = g_row_ptr[d] + atomicAdd(&g_cursor[d], 1);
            g_csr[pos] = make_int2(s, __float_as_int(ew[e]));
        }
    } else if (e < E2C) {
        int v = e - N_EDGESC;
        int pos = g_row_ptr[v] + atomicAdd(&g_cursor[v], 1);
        g_csr[pos] = make_int2(v, __float_as_int(g_loop_attr[v]));
    }
}

// ---------------- tensor-core linear (3xTF32): y = x@W^T + b --------------------
// wmma m16n16k8, fp32 accumulate. A split hi/lo in-kernel; B pre-split (g_whi/lo).
// role = blockIdx parity (l/r). Warp computes 32 nodes x DO (2 m-tiles, NT n-tiles,
// B fragments amortized over both m-tiles). Epilogue stages via smem for bias add
// and coalesced float4 stores.
template <int DI, int DO, int PAIR>
__global__ void __launch_bounds__(256) linear_tc_kernel(
    const float* __restrict__ xparam,
    const float* __restrict__ bl, const float* __restrict__ br,
    int insel) {
    constexpr int NT  = DO / 16;
    constexpr int DOP = DO + 4;
    const float* __restrict__ x = lin_in_ptr(xparam, insel);
    int role = blockIdx.x & 1;
    int tile = blockIdx.x >> 1;
    const int wbase = PAIR ? (16384 + role * 2048) : (role * 8192);
    const float* __restrict__ bia = role ? br : bl;
    float* __restrict__ y = PAIR ? (role ? g_xr2 : g_xl2) : (role ? g_xr : g_xl);
    int warp = threadIdx.x >> 5;
    int lane = threadIdx.x & 31;
    int node0 = tile * 256 + warp * 32;
    __shared__ __align__(16) float stage[8][16 * DOP];
    if (node0 >= N_NODESC) return;
    bool act1 = (node0 + 16) < N_NODESC;   // nodes are 16-granular (50000%16==0)

    wmma::fragment<wmma::accumulator, 16, 16, 8, float> acc[2][NT];
#pragma unroll
    for (int mt = 0; mt < 2; mt++)
#pragma unroll
        for (int nt = 0; nt < NT; nt++) wmma::fill_fragment(acc[mt][nt], 0.f);

    wmma::fragment<wmma::matrix_a, 16, 16, 8, wmma::precision::tf32, wmma::row_major> ahi[2], alo[2];
    wmma::fragment<wmma::matrix_b, 16, 16, 8, wmma::precision::tf32, wmma::col_major> bhi, blo;

    for (int k0 = 0; k0 < DI; k0 += 8) {
        wmma::load_matrix_sync(ahi[0], x + (size_t)node0 * DI + k0, DI);
#pragma unroll
        for (int q = 0; q < ahi[0].num_elements; q++) {
            float f = ahi[0].x[q];
            float h = wmma::__float_to_tf32(f);
            alo[0].x[q] = wmma::__float_to_tf32(f - h);
            ahi[0].x[q] = h;
        }
        if (act1) {
            wmma::load_matrix_sync(ahi[1], x + (size_t)(node0 + 16) * DI + k0, DI);
#pragma unroll
            for (int q = 0; q < ahi[1].num_elements; q++) {
                float f = ahi[1].x[q];
                float h = wmma::__float_to_tf32(f);
                alo[1].x[q] = wmma::__float_to_tf32(f - h);
                ahi[1].x[q] = h;
            }
        }
#pragma unroll
        for (int nt = 0; nt < NT; nt++) {
            wmma::load_matrix_sync(bhi, g_whi + wbase + nt * 16 * DI + k0, DI);
            wmma::load_matrix_sync(blo, g_wlo + wbase + nt * 16 * DI + k0, DI);
            wmma::mma_sync(acc[0][nt], ahi[0], bhi, acc[0][nt]);
            wmma::mma_sync(acc[0][nt], alo[0], bhi, acc[0][nt]);
            wmma::mma_sync(acc[0][nt], ahi[0], blo, acc[0][nt]);
            if (act1) {
                wmma::mma_sync(acc[1][nt], ahi[1], bhi, acc[1][nt]);
                wmma::mma_sync(acc[1][nt], alo[1], bhi, acc[1][nt]);
                wmma::mma_sync(acc[1][nt], ahi[1], blo, acc[1][nt]);
            }
        }
    }

    // epilogue: stage each 16xDO m-tile in smem, add bias, float4 store
    for (int mt = 0; mt < 2; mt++) {
        if (mt == 1 && !act1) break;
#pragma unroll
        for (int nt = 0; nt < NT; nt++)
            wmma::store_matrix_sync(&stage[warp][nt * 16], acc[mt][nt], DOP, wmma::mem_row_major);
        __syncwarp();
        int base = node0 + mt * 16;
        for (int i = lane; i < 16 * (DO / 4); i += 32) {
            int row = i / (DO / 4);
            int q   = i % (DO / 4);
            float4 v  = *reinterpret_cast<const float4*>(&stage[warp][row * DOP + q * 4]);
            float4 bb = *reinterpret_cast<const float4*>(&bia[q * 4]);
            v.x += bb.x; v.y += bb.y; v.z += bb.z; v.w += bb.w;
            *reinterpret_cast<float4*>(&y[(size_t)(base + row) * DO + q * 4]) = v;
        }
        __syncwarp();
    }
}

// ---------------- GATv2 node kernel: warp per node, 2-edge ILP (R13 champion) ---
template <int DH, int LAYER>
__global__ void __launch_bounds__(256) gat_node_kernel(
    const float* __restrict__ We, const float* __restrict__ att,
    const float* __restrict__ bias, float* __restrict__ outp) {
    constexpr int PER = DH / 32;
    const float* __restrict__ xl = (LAYER == 0) ? g_xl : g_xl2;
    const float* __restrict__ xr = (LAYER == 0) ? g_xr : g_xr2;
    float* __restrict__ out = (LAYER == 0) ? g_h : outp;
    int gi = blockIdx.x * blockDim.x + threadIdx.x;
    if (LAYER == 0 && gi < N_NODESC) {           // restore zero-invariant
        g_count[gi] = 0;
        g_attr_sum[gi] = 0.f;
        g_cursor[gi] = 0;
    }
    int v    = gi >> 5;
    int lane = gi & 31;
    if (v >= N_NODESC) return;

    float xrv[PER], wev[PER], attv[PER], bv[PER];
#pragma unroll
    for (int p = 0; p < PER; p++) {
        int h = lane * PER + p;
        xrv[p]  = xr[v * DH + h];
        wev[p]  = We[h];
        attv[p] = att[h];
        bv[p]   = bias[h];
    }
    int beg = g_row_ptr[v], end = g_row_ptr[v + 1];   // end > beg (self loop)

    float ssum = 0.f;
    float acc[PER];
#pragma unroll
    for (int p = 0; p < PER; p++) acc[p] = 0.f;

    int idx = beg;
    for (; idx + 1 < end; idx += 2) {
        int2 e0 = g_csr[idx];
        int2 e1 = g_csr[idx + 1];
        const float* p0 = xl + (size_t)e0.x * DH + lane * PER;
        const float* p1 = xl + (size_t)e1.x * DH + lane * PER;
        float x0[PER], x1[PER];
        if (PER == 2) {
            float2 t0 = *reinterpret_cast<const float2*>(p0);
            float2 t1 = *reinterpret_cast<const float2*>(p1);
            x0[0] = t0.x; x0[1] = t0.y;
            x1[0] = t1.x; x1[1] = t1.y;
        } else {
            x0[0] = *p0; x1[0] = *p1;
        }
        float a0 = __int_as_float(e0.y);
        float a1 = __int_as_float(e1.y);
        float sc0 = 0.f, sc1 = 0.f;
#pragma unroll
        for (int p = 0; p < PER; p++) {
            float m0 = x0[p] + xrv[p] + a0 * wev[p];
            float m1 = x1[p] + xrv[p] + a1 * wev[p];
            m0 = m0 > 0.f ? m0 : 0.2f * m0;
            m1 = m1 > 0.f ? m1 : 0.2f * m1;
            sc0 = fmaf(attv[p], m0, sc0);
            sc1 = fmaf(attv[p], m1, sc1);
        }
#pragma unroll
        for (int o = 16; o; o >>= 1) {
            sc0 += __shfl_xor_sync(0xffffffffu, sc0, o);
            sc1 += __shfl_xor_sync(0xffffffffu, sc1, o);
        }
        float ex0 = __expf(sc0);
        float ex1 = __expf(sc1);
        ssum += ex0 + ex1;
#pragma unroll
        for (int p = 0; p < PER; p++) {
            acc[p] = fmaf(ex0, x0[p], acc[p]);
            acc[p] = fmaf(ex1, x1[p], acc[p]);
        }
    }
    if (idx < end) {                       // odd tail
        int2 e0 = g_csr[idx];
        const float* p0 = xl + (size_t)e0.x * DH + lane * PER;
        float x0[PER];
        if (PER == 2) {
            float2 t0 = *reinterpret_cast<const float2*>(p0);
            x0[0] = t0.x; x0[1] = t0.y;
        } else {
            x0[0] = *p0;
        }
        float a0 = __int_as_float(e0.y);
        float sc0 = 0.f;
#pragma unroll
        for (int p = 0; p < PER; p++) {
            float m0 = x0[p] + xrv[p] + a0 * wev[p];
            m0 = m0 > 0.f ? m0 : 0.2f * m0;
            sc0 = fmaf(attv[p], m0, sc0);
        }
#pragma unroll
        for (int o = 16; o; o >>= 1) sc0 += __shfl_xor_sync(0xffffffffu, sc0, o);
        float ex0 = __expf(sc0);
        ssum += ex0;
#pragma unroll
        for (int p = 0; p < PER; p++) acc[p] = fmaf(ex0, x0[p], acc[p]);
    }

    float inv = 1.f / ssum;
#pragma unroll
    for (int p = 0; p < PER; p++) {
        float o = fmaf(acc[p], inv, bv[p]);
        if (LAYER == 0) {
            o = o > 0.f ? o : (__expf(o) - 1.f);            // elu
        } else {
            o = (o > 20.f ? o : log1pf(__expf(o))) + 1e-4f; // softplus + eps
        }
        out[v * DH + lane * PER + p] = o;
    }
}

// ---------------- launch --------------------------------------------------------
extern "C" void kernel_launch(void* const* d_in, const int* in_sizes, int n_in,
                              void* d_out, int out_size) {
    const float* x     = (const float*)d_in[0];
    const int*   ei    = (const int*)d_in[1];      // edge_index: int32
    const float* ew    = (const float*)d_in[2];
    const float* Wl1   = (const float*)d_in[3];
    const float* bl1   = (const float*)d_in[4];
    const float* Wr1   = (const float*)d_in[5];
    const float* br1   = (const float*)d_in[6];
    const float* We1   = (const float*)d_in[7];
    const float* att1  = (const float*)d_in[8];
    const float* bias1 = (const float*)d_in[9];
    const float* Wl2   = (const float*)d_in[10];
    const float* bl2   = (const float*)d_in[11];
    const float* Wr2   = (const float*)d_in[12];
    const float* br2   = (const float*)d_in[13];
    const float* We2   = (const float*)d_in[14];
    const float* att2  = (const float*)d_in[15];
    const float* bias2 = (const float*)d_in[16];
    float*       out   = (float*)d_out;

    // ---- W hi/lo split + graph preprocessing (counters zero by invariant) ----
    wsplit_kernel<<<(W_SPLIT_TOTAL + 255) / 256, 256>>>(Wl1, Wr1, Wl2, Wr2);
    count_kernel<<<(N_EDGESC + 255) / 256, 256>>>(ei, ew);
    scan1_kernel<<<SCAN_GRID, SCAN_BLK>>>();
    scan2_kernel<<<1, SCAN_BLK>>>();
    scan3_kernel<<<SCAN_GRID, SCAN_BLK>>>();
    scatter_kernel<<<(E2C + 255) / 256, 256>>>(ei, ew);

    const int GRID_GAT = (N_NODESC * 32 + 255) / 256;        // warp per node
    const int GRID_TC  = 2 * ((N_NODESC + 255) / 256);       // 2 roles x 196

    // ---- layer 1 ----
    linear_tc_kernel<D_INC, D_HIDC, 0><<<GRID_TC, 256>>>(x, bl1, br1, 0);
    gat_node_kernel<D_HIDC, 0><<<GRID_GAT, 256>>>(We1, att1, bias1, out);

    // ---- layer 2 (input = g_h via insel=1) ----
    linear_tc_kernel<D_HIDC, D_OUTC, 1><<<GRID_TC, 256>>>(x, bl2, br2, 1);
    gat_node_kernel<D_OUTC, 1><<<GRID_GAT, 256>>>(We2, att2, bias2, out);
}

// round 15
// speedup vs baseline: 1.2165x; 1.2165x over previous
#include <cuda_runtime.h>

#define N_NODESC 50000
#define N_EDGESC 800000
#define E2C (N_EDGESC + N_NODESC)
#define D_INC 128
#define D_HIDC 64
#define D_OUTC 32
#define SCAN_BLK 256
#define SCAN_GRID ((N_NODESC + SCAN_BLK - 1) / SCAN_BLK)   // 196

// ---------------- scratch (device globals; never referenced from host) --------
// Zero-initialized at module load; gat layer-0 kernel re-zeros the consumed
// counters each call (measured free in R7/R8) so every replay sees zeros.
__device__ __align__(16) int   g_count[N_NODESC];
__device__ __align__(16) float g_attr_sum[N_NODESC];
__device__ __align__(16) float g_loop_attr[N_NODESC];
__device__ __align__(16) int   g_row_ptr[N_NODESC + 1];
__device__ __align__(16) int   g_cursor[N_NODESC];
__device__ __align__(16) int2  g_csr[E2C];                 // (src, attr-bits)
__device__ __align__(16) int   g_bsum[SCAN_GRID];
__device__ __align__(16) float g_xl [N_NODESC * D_HIDC];
__device__ __align__(16) float g_xr [N_NODESC * D_HIDC];
__device__ __align__(16) float g_h  [N_NODESC * D_HIDC];
__device__ __align__(16) float g_xl2[N_NODESC * D_OUTC];
__device__ __align__(16) float g_xr2[N_NODESC * D_OUTC];

__device__ __forceinline__ const float* lin_in_ptr(const float* xparam, int sel) {
    return (sel == 0) ? xparam : g_h;
}

// ---------------- preprocessing (multi-block; scan2 merged into scan3) ----------
__global__ void count_kernel(const int* __restrict__ ei,
                             const float* __restrict__ ew) {
    int e = blockIdx.x * blockDim.x + threadIdx.x;
    if (e < N_EDGESC) {
        int d = ei[N_EDGESC + e];
        if ((unsigned)d < (unsigned)N_NODESC) {
            atomicAdd(&g_count[d], 1);
            atomicAdd(&g_attr_sum[d], ew[e]);
        }
    }
}

__global__ void scan1_kernel() {   // per-block sums + loop_attr
    __shared__ int red[SCAN_BLK];
    int t = threadIdx.x, b = blockIdx.x;
    int i = b * SCAN_BLK + t;
    int val = 0;
    if (i < N_NODESC) {
        int c = g_count[i];
        val = c + 1;
        g_loop_attr[i] = g_attr_sum[i] / fmaxf((float)c, 1.0f);
    }
    red[t] = val;
    __syncthreads();
#pragma unroll
    for (int off = SCAN_BLK / 2; off > 0; off >>= 1) {
        if (t < off) red[t] += red[t + off];
        __syncthreads();
    }
    if (t == 0) g_bsum[b] = red[0];
}

// local scan + (redundant in-block scan of the 196 block sums) -> row_ptr
__global__ void scan3_kernel() {
    __shared__ int sh[SCAN_BLK];
    __shared__ int pref[SCAN_BLK];
    int t = threadIdx.x, b = blockIdx.x;
    // inclusive scan of block sums (redundant per block; replaces scan2 launch)
    int bs = (t < SCAN_GRID) ? g_bsum[t] : 0;
    pref[t] = bs;
    __syncthreads();
    for (int off = 1; off < SCAN_BLK; off <<= 1) {
        int v = (t >= off) ? pref[t - off] : 0;
        __syncthreads();
        pref[t] += v;
        __syncthreads();
    }
    int boff = (b == 0) ? 0 : pref[b - 1];
    // local scan
    int i = b * SCAN_BLK + t;
    int val = (i < N_NODESC) ? (g_count[i] + 1) : 0;
    sh[t] = val;
    __syncthreads();
    for (int off = 1; off < SCAN_BLK; off <<= 1) {
        int v = (t >= off) ? sh[t - off] : 0;
        __syncthreads();
        sh[t] += v;
        __syncthreads();
    }
    if (i < N_NODESC) g_row_ptr[i] = boff + sh[t] - val;
    if (i == N_NODESC) g_row_ptr[N_NODESC] = E2C;
}

__global__ void scatter_kernel(const int* __restrict__ ei,
                               const float* __restrict__ ew) {
    int e = blockIdx.x * blockDim.x + threadIdx.x;
    if (e < N_EDGESC) {
        int d = ei[N_EDGESC + e];
        int s = ei[e];
        if ((unsigned)d < (unsigned)N_NODESC && (unsigned)s < (unsigned)N_NODESC) {
            int pos = g_row_ptr[d] + atomicAdd(&g_cursor[d], 1);
            g_csr[pos] = make_int2(s, __float_as_int(ew[e]));
        }
    } else if (e < E2C) {
        int v = e - N_EDGESC;
        int pos = g_row_ptr[v] + atomicAdd(&g_cursor[v], 1);
        g_csr[pos] = make_int2(v, __float_as_int(g_loop_attr[v]));
    }
}

// ---------------- fused linear: yl = x@Wl^T+bl, yr = x@Wr^T+br ------------------
// R10/R12/R13-measured form (62.6us layer 1): R_N=4, XS=TN+1, scalar x LDS.
template <int DI, int DO, int TN, int KC, int PAIR>
__global__ void __launch_bounds__(256) linear_fused_kernel(
    const float* __restrict__ xparam,
    const float* __restrict__ Wl, const float* __restrict__ bl,
    const float* __restrict__ Wr, const float* __restrict__ br,
    int insel) {
    constexpr int WS   = DO + 4;
    constexpr int XS   = TN + 1;
    constexpr int NT_H = DO / 4;
    constexpr int NT_N = 256 / NT_H;
    constexpr int R_N  = TN / NT_N;
    static_assert(DI % KC == 0 && R_N == 4, "tile config");
    __shared__ __align__(16) float Wls[KC * WS];
    __shared__ __align__(16) float Wrs[KC * WS];
    __shared__ __align__(16) float xs[KC * XS];
    const float* __restrict__ x = lin_in_ptr(xparam, insel);
    float* __restrict__ yl = PAIR ? g_xl2 : g_xl;
    float* __restrict__ yr = PAIR ? g_xr2 : g_xr;
    int t = threadIdx.x;
    int node0 = blockIdx.x * TN;
    int h0 = (t % NT_H) * 4;
    int n0 = (t / NT_H) * R_N;
    float accl[R_N][4], accr[R_N][4];
#pragma unroll
    for (int r = 0; r < R_N; r++)
#pragma unroll
        for (int c = 0; c < 4; c++) { accl[r][c] = 0.f; accr[r][c] = 0.f; }

    for (int c = 0; c < DI / KC; c++) {
        if (c) __syncthreads();
        for (int i = t; i < DO * KC; i += 256) {
            int r = i / KC, k = i % KC;
            Wls[k * WS + r] = Wl[r * DI + c * KC + k];
            Wrs[k * WS + r] = Wr[r * DI + c * KC + k];
        }
        for (int i = t; i < TN * KC; i += 256) {
            int n = i / KC, k = i % KC;
            int nd = node0 + n;
            xs[k * XS + n] = (nd < N_NODESC) ? x[nd * DI + c * KC + k] : 0.f;
        }
        __syncthreads();
#pragma unroll 4
        for (int k = 0; k < KC; k++) {
            float4 wl4 = *reinterpret_cast<const float4*>(&Wls[k * WS + h0]);
            float4 wr4 = *reinterpret_cast<const float4*>(&Wrs[k * WS + h0]);
            float xvr[R_N];
#pragma unroll
            for (int r = 0; r < R_N; r++) xvr[r] = xs[k * XS + n0 + r];
#pragma unroll
            for (int r = 0; r < R_N; r++) {
                accl[r][0] = fmaf(xvr[r], wl4.x, accl[r][0]);
                accl[r][1] = fmaf(xvr[r], wl4.y, accl[r][1]);
                accl[r][2] = fmaf(xvr[r], wl4.z, accl[r][2]);
                accl[r][3] = fmaf(xvr[r], wl4.w, accl[r][3]);
                accr[r][0] = fmaf(xvr[r], wr4.x, accr[r][0]);
                accr[r][1] = fmaf(xvr[r], wr4.y, accr[r][1]);
                accr[r][2] = fmaf(xvr[r], wr4.z, accr[r][2]);
                accr[r][3] = fmaf(xvr[r], wr4.w, accr[r][3]);
            }
        }
    }
#pragma unroll
    for (int r = 0; r < R_N; r++) {
        int node = node0 + n0 + r;
        if (node < N_NODESC) {
            float4 o;
            o.x = accl[r][0] + bl[h0 + 0];
            o.y = accl[r][1] + bl[h0 + 1];
            o.z = accl[r][2] + bl[h0 + 2];
            o.w = accl[r][3] + bl[h0 + 3];
            *reinterpret_cast<float4*>(&yl[node * DO + h0]) = o;
            o.x = accr[r][0] + br[h0 + 0];
            o.y = accr[r][1] + br[h0 + 1];
            o.z = accr[r][2] + br[h0 + 2];
            o.w = accr[r][3] + br[h0 + 3];
            *reinterpret_cast<float4*>(&yr[node * DO + h0]) = o;
        }
    }
}

// ---------------- GATv2 node kernel: warp per node, 4-edge ILP ------------------
// Extends the measured 2-edge win (gat1 53->43): 4 edges per iteration amortizes
// loop overhead further, quadruples gather MLP, interleaves 4 shuffle chains.
// LAYER 0 additionally re-zeros the preprocessing counters for the next replay.
template <int DH, int LAYER>
__global__ void __launch_bounds__(256) gat_node_kernel(
    const float* __restrict__ We, const float* __restrict__ att,
    const float* __restrict__ bias, float* __restrict__ outp) {
    constexpr int PER = DH / 32;
    const float* __restrict__ xl = (LAYER == 0) ? g_xl : g_xl2;
    const float* __restrict__ xr = (LAYER == 0) ? g_xr : g_xr2;
    float* __restrict__ out = (LAYER == 0) ? g_h : outp;
    int gi = blockIdx.x * blockDim.x + threadIdx.x;
    if (LAYER == 0 && gi < N_NODESC) {           // restore zero-invariant
        g_count[gi] = 0;
        g_attr_sum[gi] = 0.f;
        g_cursor[gi] = 0;
    }
    int v    = gi >> 5;
    int lane = gi & 31;
    if (v >= N_NODESC) return;

    float xrv[PER], wev[PER], attv[PER], bv[PER];
#pragma unroll
    for (int p = 0; p < PER; p++) {
        int h = lane * PER + p;
        xrv[p]  = xr[v * DH + h];
        wev[p]  = We[h];
        attv[p] = att[h];
        bv[p]   = bias[h];
    }
    int beg = g_row_ptr[v], end = g_row_ptr[v + 1];   // end > beg (self loop)

    float ssum = 0.f;
    float acc[PER];
#pragma unroll
    for (int p = 0; p < PER; p++) acc[p] = 0.f;

    int idx = beg;
    for (; idx + 3 < end; idx += 4) {
        int2 e[4];
        float xv[4][PER], a[4], sc[4];
#pragma unroll
        for (int j = 0; j < 4; j++) e[j] = g_csr[idx + j];
#pragma unroll
        for (int j = 0; j < 4; j++) {
            const float* pj = xl + (size_t)e[j].x * DH + lane * PER;
            if (PER == 2) {
                float2 t2 = *reinterpret_cast<const float2*>(pj);
                xv[j][0] = t2.x; xv[j][1] = t2.y;
            } else {
                xv[j][0] = *pj;
            }
            a[j] = __int_as_float(e[j].y);
            sc[j] = 0.f;
        }
#pragma unroll
        for (int j = 0; j < 4; j++) {
#pragma unroll
            for (int p = 0; p < PER; p++) {
                float m = xv[j][p] + xrv[p] + a[j] * wev[p];
                m = m > 0.f ? m : 0.2f * m;
                sc[j] = fmaf(attv[p], m, sc[j]);
            }
        }
#pragma unroll
        for (int o = 16; o; o >>= 1) {
#pragma unroll
            for (int j = 0; j < 4; j++)
                sc[j] += __shfl_xor_sync(0xffffffffu, sc[j], o);
        }
#pragma unroll
        for (int j = 0; j < 4; j++) {
            float ex = __expf(sc[j]);
            ssum += ex;
#pragma unroll
            for (int p = 0; p < PER; p++) acc[p] = fmaf(ex, xv[j][p], acc[p]);
        }
    }
    for (; idx < end; idx++) {            // tail: up to 3 edges
        int2 e0 = g_csr[idx];
        const float* p0 = xl + (size_t)e0.x * DH + lane * PER;
        float x0[PER];
        if (PER == 2) {
            float2 t0 = *reinterpret_cast<const float2*>(p0);
            x0[0] = t0.x; x0[1] = t0.y;
        } else {
            x0[0] = *p0;
        }
        float a0 = __int_as_float(e0.y);
        float sc0 = 0.f;
#pragma unroll
        for (int p = 0; p < PER; p++) {
            float m0 = x0[p] + xrv[p] + a0 * wev[p];
            m0 = m0 > 0.f ? m0 : 0.2f * m0;
            sc0 = fmaf(attv[p], m0, sc0);
        }
#pragma unroll
        for (int o = 16; o; o >>= 1) sc0 += __shfl_xor_sync(0xffffffffu, sc0, o);
        float ex0 = __expf(sc0);
        ssum += ex0;
#pragma unroll
        for (int p = 0; p < PER; p++) acc[p] = fmaf(ex0, x0[p], acc[p]);
    }

    float inv = 1.f / ssum;
#pragma unroll
    for (int p = 0; p < PER; p++) {
        float o = fmaf(acc[p], inv, bv[p]);
        if (LAYER == 0) {
            o = o > 0.f ? o : (__expf(o) - 1.f);            // elu
        } else {
            o = (o > 20.f ? o : log1pf(__expf(o))) + 1e-4f; // softplus + eps
        }
        out[v * DH + lane * PER + p] = o;
    }
}

// ---------------- launch --------------------------------------------------------
extern "C" void kernel_launch(void* const* d_in, const int* in_sizes, int n_in,
                              void* d_out, int out_size) {
    const float* x     = (const float*)d_in[0];
    const int*   ei    = (const int*)d_in[1];      // edge_index: int32
    const float* ew    = (const float*)d_in[2];
    const float* Wl1   = (const float*)d_in[3];
    const float* bl1   = (const float*)d_in[4];
    const float* Wr1   = (const float*)d_in[5];
    const float* br1   = (const float*)d_in[6];
    const float* We1   = (const float*)d_in[7];
    const float* att1  = (const float*)d_in[8];
    const float* bias1 = (const float*)d_in[9];
    const float* Wl2   = (const float*)d_in[10];
    const float* bl2   = (const float*)d_in[11];
    const float* Wr2   = (const float*)d_in[12];
    const float* br2   = (const float*)d_in[13];
    const float* We2   = (const float*)d_in[14];
    const float* att2  = (const float*)d_in[15];
    const float* bias2 = (const float*)d_in[16];
    float*       out   = (float*)d_out;

    // ---- graph preprocessing / CSR (counters zero by invariant) ----
    count_kernel<<<(N_EDGESC + 255) / 256, 256>>>(ei, ew);
    scan1_kernel<<<SCAN_GRID, SCAN_BLK>>>();
    scan3_kernel<<<SCAN_GRID, SCAN_BLK>>>();
    scatter_kernel<<<(E2C + 255) / 256, 256>>>(ei, ew);

    const int GRID_GAT = (N_NODESC * 32 + 255) / 256;   // warp per node

    // ---- layer 1 (TN=64, KC=32, R_N=4) ----
    linear_fused_kernel<D_INC, D_HIDC, 64, 32, 0><<<(N_NODESC + 63) / 64, 256>>>(
        x, Wl1, bl1, Wr1, br1, 0);
    gat_node_kernel<D_HIDC, 0><<<GRID_GAT, 256>>>(We1, att1, bias1, out);

    // ---- layer 2 (input = g_h via insel=1; TN=128, KC=32, R_N=4) ----
    linear_fused_kernel<D_HIDC, D_OUTC, 128, 32, 1><<<(N_NODESC + 127) / 128, 256>>>(
        x, Wl2, bl2, Wr2, br2, 1);
    gat_node_kernel<D_OUTC, 1><<<GRID_GAT, 256>>>(We2, att2, bias2, out);
}

// round 16
// speedup vs baseline: 1.3394x; 1.1010x over previous
#include <cuda_runtime.h>

#define N_NODESC 50000
#define N_EDGESC 800000
#define E2C (N_EDGESC + N_NODESC)
#define D_INC 128
#define D_HIDC 64
#define D_OUTC 32
#define SCAN_BLK 256
#define SCAN_GRID ((N_NODESC + SCAN_BLK - 1) / SCAN_BLK)   // 196

// ---------------- scratch (device globals; never referenced from host) --------
// Zero-initialized at module load; gat layer-0 kernel re-zeros the consumed
// counters each call (measured free in R7/R8) so every replay sees zeros.
__device__ __align__(16) int   g_count[N_NODESC];
__device__ __align__(16) float g_attr_sum[N_NODESC];
__device__ __align__(16) float g_loop_attr[N_NODESC];
__device__ __align__(16) int   g_row_ptr[N_NODESC + 1];
__device__ __align__(16) int   g_cursor[N_NODESC];
__device__ __align__(16) int2  g_csr[E2C];                 // (src, attr-bits)
__device__ __align__(16) int   g_bsum[SCAN_GRID];
__device__ __align__(16) float g_xl [N_NODESC * D_HIDC];
__device__ __align__(16) float g_xr [N_NODESC * D_HIDC];
__device__ __align__(16) float g_h  [N_NODESC * D_HIDC];
__device__ __align__(16) float g_xl2[N_NODESC * D_OUTC];
__device__ __align__(16) float g_xr2[N_NODESC * D_OUTC];

__device__ __forceinline__ const float* lin_in_ptr(const float* xparam, int sel) {
    return (sel == 0) ? xparam : g_h;
}

// ---------------- preprocessing (multi-block; scan2 merged into scan3) ----------
__global__ void count_kernel(const int* __restrict__ ei,
                             const float* __restrict__ ew) {
    int e = blockIdx.x * blockDim.x + threadIdx.x;
    if (e < N_EDGESC) {
        int d = ei[N_EDGESC + e];
        if ((unsigned)d < (unsigned)N_NODESC) {
            atomicAdd(&g_count[d], 1);
            atomicAdd(&g_attr_sum[d], ew[e]);
        }
    }
}

__global__ void scan1_kernel() {   // per-block sums + loop_attr
    __shared__ int red[SCAN_BLK];
    int t = threadIdx.x, b = blockIdx.x;
    int i = b * SCAN_BLK + t;
    int val = 0;
    if (i < N_NODESC) {
        int c = g_count[i];
        val = c + 1;
        g_loop_attr[i] = g_attr_sum[i] / fmaxf((float)c, 1.0f);
    }
    red[t] = val;
    __syncthreads();
#pragma unroll
    for (int off = SCAN_BLK / 2; off > 0; off >>= 1) {
        if (t < off) red[t] += red[t + off];
        __syncthreads();
    }
    if (t == 0) g_bsum[b] = red[0];
}

// local scan + (redundant in-block scan of the 196 block sums) -> row_ptr
__global__ void scan3_kernel() {
    __shared__ int sh[SCAN_BLK];
    __shared__ int pref[SCAN_BLK];
    int t = threadIdx.x, b = blockIdx.x;
    int bs = (t < SCAN_GRID) ? g_bsum[t] : 0;
    pref[t] = bs;
    __syncthreads();
    for (int off = 1; off < SCAN_BLK; off <<= 1) {
        int v = (t >= off) ? pref[t - off] : 0;
        __syncthreads();
        pref[t] += v;
        __syncthreads();
    }
    int boff = (b == 0) ? 0 : pref[b - 1];
    int i = b * SCAN_BLK + t;
    int val = (i < N_NODESC) ? (g_count[i] + 1) : 0;
    sh[t] = val;
    __syncthreads();
    for (int off = 1; off < SCAN_BLK; off <<= 1) {
        int v = (t >= off) ? sh[t - off] : 0;
        __syncthreads();
        sh[t] += v;
        __syncthreads();
    }
    if (i < N_NODESC) g_row_ptr[i] = boff + sh[t] - val;
    if (i == N_NODESC) g_row_ptr[N_NODESC] = E2C;
}

__global__ void scatter_kernel(const int* __restrict__ ei,
                               const float* __restrict__ ew) {
    int e = blockIdx.x * blockDim.x + threadIdx.x;
    if (e < N_EDGESC) {
        int d = ei[N_EDGESC + e];
        int s = ei[e];
        if ((unsigned)d < (unsigned)N_NODESC && (unsigned)s < (unsigned)N_NODESC) {
            int pos = g_row_ptr[d] + atomicAdd(&g_cursor[d], 1);
            g_csr[pos] = make_int2(s, __float_as_int(ew[e]));
        }
    } else if (e < E2C) {
        int v = e - N_EDGESC;
        int pos = g_row_ptr[v] + atomicAdd(&g_cursor[v], 1);
        g_csr[pos] = make_int2(v, __float_as_int(g_loop_attr[v]));
    }
}

// ---------------- fused linear: yl = x@Wl^T+bl, yr = x@Wr^T+br ------------------
// R10/R12/R13/R15-measured form (62.6us layer 1): R_N=4, XS=TN+1, scalar x LDS.
template <int DI, int DO, int TN, int KC, int PAIR>
__global__ void __launch_bounds__(256) linear_fused_kernel(
    const float* __restrict__ xparam,
    const float* __restrict__ Wl, const float* __restrict__ bl,
    const float* __restrict__ Wr, const float* __restrict__ br,
    int insel) {
    constexpr int WS   = DO + 4;
    constexpr int XS   = TN + 1;
    constexpr int NT_H = DO / 4;
    constexpr int NT_N = 256 / NT_H;
    constexpr int R_N  = TN / NT_N;
    static_assert(DI % KC == 0 && R_N == 4, "tile config");
    __shared__ __align__(16) float Wls[KC * WS];
    __shared__ __align__(16) float Wrs[KC * WS];
    __shared__ __align__(16) float xs[KC * XS];
    const float* __restrict__ x = lin_in_ptr(xparam, insel);
    float* __restrict__ yl = PAIR ? g_xl2 : g_xl;
    float* __restrict__ yr = PAIR ? g_xr2 : g_xr;
    int t = threadIdx.x;
    int node0 = blockIdx.x * TN;
    int h0 = (t % NT_H) * 4;
    int n0 = (t / NT_H) * R_N;
    float accl[R_N][4], accr[R_N][4];
#pragma unroll
    for (int r = 0; r < R_N; r++)
#pragma unroll
        for (int c = 0; c < 4; c++) { accl[r][c] = 0.f; accr[r][c] = 0.f; }

    for (int c = 0; c < DI / KC; c++) {
        if (c) __syncthreads();
        for (int i = t; i < DO * KC; i += 256) {
            int r = i / KC, k = i % KC;
            Wls[k * WS + r] = Wl[r * DI + c * KC + k];
            Wrs[k * WS + r] = Wr[r * DI + c * KC + k];
        }
        for (int i = t; i < TN * KC; i += 256) {
            int n = i / KC, k = i % KC;
            int nd = node0 + n;
            xs[k * XS + n] = (nd < N_NODESC) ? x[nd * DI + c * KC + k] : 0.f;
        }
        __syncthreads();
#pragma unroll 4
        for (int k = 0; k < KC; k++) {
            float4 wl4 = *reinterpret_cast<const float4*>(&Wls[k * WS + h0]);
            float4 wr4 = *reinterpret_cast<const float4*>(&Wrs[k * WS + h0]);
            float xvr[R_N];
#pragma unroll
            for (int r = 0; r < R_N; r++) xvr[r] = xs[k * XS + n0 + r];
#pragma unroll
            for (int r = 0; r < R_N; r++) {
                accl[r][0] = fmaf(xvr[r], wl4.x, accl[r][0]);
                accl[r][1] = fmaf(xvr[r], wl4.y, accl[r][1]);
                accl[r][2] = fmaf(xvr[r], wl4.z, accl[r][2]);
                accl[r][3] = fmaf(xvr[r], wl4.w, accl[r][3]);
                accr[r][0] = fmaf(xvr[r], wr4.x, accr[r][0]);
                accr[r][1] = fmaf(xvr[r], wr4.y, accr[r][1]);
                accr[r][2] = fmaf(xvr[r], wr4.z, accr[r][2]);
                accr[r][3] = fmaf(xvr[r], wr4.w, accr[r][3]);
            }
        }
    }
#pragma unroll
    for (int r = 0; r < R_N; r++) {
        int node = node0 + n0 + r;
        if (node < N_NODESC) {
            float4 o;
            o.x = accl[r][0] + bl[h0 + 0];
            o.y = accl[r][1] + bl[h0 + 1];
            o.z = accl[r][2] + bl[h0 + 2];
            o.w = accl[r][3] + bl[h0 + 3];
            *reinterpret_cast<float4*>(&yl[node * DO + h0]) = o;
            o.x = accr[r][0] + br[h0 + 0];
            o.y = accr[r][1] + br[h0 + 1];
            o.z = accr[r][2] + br[h0 + 2];
            o.w = accr[r][3] + br[h0 + 3];
            *reinterpret_cast<float4*>(&yr[node * DO + h0]) = o;
        }
    }
}

// ---------------- GATv2 node kernel: warp per node, 4-edge ILP (R15 champion) ---
template <int DH, int LAYER>
__global__ void __launch_bounds__(256) gat_node_kernel(
    const float* __restrict__ We, const float* __restrict__ att,
    const float* __restrict__ bias, float* __restrict__ outp) {
    constexpr int PER = DH / 32;
    const float* __restrict__ xl = (LAYER == 0) ? g_xl : g_xl2;
    const float* __restrict__ xr = (LAYER == 0) ? g_xr : g_xr2;
    float* __restrict__ out = (LAYER == 0) ? g_h : outp;
    int gi = blockIdx.x * blockDim.x + threadIdx.x;
    if (LAYER == 0 && gi < N_NODESC) {           // restore zero-invariant
        g_count[gi] = 0;
        g_attr_sum[gi] = 0.f;
        g_cursor[gi] = 0;
    }
    int v    = gi >> 5;
    int lane = gi & 31;
    if (v >= N_NODESC) return;

    float xrv[PER], wev[PER], attv[PER], bv[PER];
#pragma unroll
    for (int p = 0; p < PER; p++) {
        int h = lane * PER + p;
        xrv[p]  = xr[v * DH + h];
        wev[p]  = We[h];
        attv[p] = att[h];
        bv[p]   = bias[h];
    }
    int beg = g_row_ptr[v], end = g_row_ptr[v + 1];   // end > beg (self loop)

    float ssum = 0.f;
    float acc[PER];
#pragma unroll
    for (int p = 0; p < PER; p++) acc[p] = 0.f;

    int idx = beg;
    for (; idx + 3 < end; idx += 4) {
        int2 e[4];
        float xv[4][PER], a[4], sc[4];
#pragma unroll
        for (int j = 0; j < 4; j++) e[j] = g_csr[idx + j];
#pragma unroll
        for (int j = 0; j < 4; j++) {
            const float* pj = xl + (size_t)e[j].x * DH + lane * PER;
            if (PER == 2) {
                float2 t2 = *reinterpret_cast<const float2*>(pj);
                xv[j][0] = t2.x; xv[j][1] = t2.y;
            } else {
                xv[j][0] = *pj;
            }
            a[j] = __int_as_float(e[j].y);
            sc[j] = 0.f;
        }
#pragma unroll
        for (int j = 0; j < 4; j++) {
#pragma unroll
            for (int p = 0; p < PER; p++) {
                float m = xv[j][p] + xrv[p] + a[j] * wev[p];
                m = m > 0.f ? m : 0.2f * m;
                sc[j] = fmaf(attv[p], m, sc[j]);
            }
        }
#pragma unroll
        for (int o = 16; o; o >>= 1) {
#pragma unroll
            for (int j = 0; j < 4; j++)
                sc[j] += __shfl_xor_sync(0xffffffffu, sc[j], o);
        }
#pragma unroll
        for (int j = 0; j < 4; j++) {
            float ex = __expf(sc[j]);
            ssum += ex;
#pragma unroll
            for (int p = 0; p < PER; p++) acc[p] = fmaf(ex, xv[j][p], acc[p]);
        }
    }
    for (; idx < end; idx++) {            // tail: up to 3 edges
        int2 e0 = g_csr[idx];
        const float* p0 = xl + (size_t)e0.x * DH + lane * PER;
        float x0[PER];
        if (PER == 2) {
            float2 t0 = *reinterpret_cast<const float2*>(p0);
            x0[0] = t0.x; x0[1] = t0.y;
        } else {
            x0[0] = *p0;
        }
        float a0 = __int_as_float(e0.y);
        float sc0 = 0.f;
#pragma unroll
        for (int p = 0; p < PER; p++) {
            float m0 = x0[p] + xrv[p] + a0 * wev[p];
            m0 = m0 > 0.f ? m0 : 0.2f * m0;
            sc0 = fmaf(attv[p], m0, sc0);
        }
#pragma unroll
        for (int o = 16; o; o >>= 1) sc0 += __shfl_xor_sync(0xffffffffu, sc0, o);
        float ex0 = __expf(sc0);
        ssum += ex0;
#pragma unroll
        for (int p = 0; p < PER; p++) acc[p] = fmaf(ex0, x0[p], acc[p]);
    }

    float inv = 1.f / ssum;
#pragma unroll
    for (int p = 0; p < PER; p++) {
        float o = fmaf(acc[p], inv, bv[p]);
        if (LAYER == 0) {
            o = o > 0.f ? o : (__expf(o) - 1.f);            // elu
        } else {
            o = (o > 20.f ? o : log1pf(__expf(o))) + 1e-4f; // softplus + eps
        }
        out[v * DH + lane * PER + p] = o;
    }
}

// ---------------- launch --------------------------------------------------------
// Two-stream fork/join inside graph capture: the CSR chain (count/scan/scatter)
// runs on a side stream concurrently with linear1 (independent buffers); both
// join before gat1. Streams/events are host objects created per call (no device
// allocation; kernel_launch runs only a handful of times).
extern "C" void kernel_launch(void* const* d_in, const int* in_sizes, int n_in,
                              void* d_out, int out_size) {
    const float* x     = (const float*)d_in[0];
    const int*   ei    = (const int*)d_in[1];      // edge_index: int32
    const float* ew    = (const float*)d_in[2];
    const float* Wl1   = (const float*)d_in[3];
    const float* bl1   = (const float*)d_in[4];
    const float* Wr1   = (const float*)d_in[5];
    const float* br1   = (const float*)d_in[6];
    const float* We1   = (const float*)d_in[7];
    const float* att1  = (const float*)d_in[8];
    const float* bias1 = (const float*)d_in[9];
    const float* Wl2   = (const float*)d_in[10];
    const float* bl2   = (const float*)d_in[11];
    const float* Wr2   = (const float*)d_in[12];
    const float* br2   = (const float*)d_in[13];
    const float* We2   = (const float*)d_in[14];
    const float* att2  = (const float*)d_in[15];
    const float* bias2 = (const float*)d_in[16];
    float*       out   = (float*)d_out;

    cudaStream_t s2;
    cudaStreamCreateWithFlags(&s2, cudaStreamNonBlocking);
    cudaEvent_t evFork, evJoin;
    cudaEventCreateWithFlags(&evFork, cudaEventDisableTiming);
    cudaEventCreateWithFlags(&evJoin, cudaEventDisableTiming);

    const int GRID_GAT = (N_NODESC * 32 + 255) / 256;   // warp per node

    // fork: side stream joins the capture graph via event dependency
    cudaEventRecord(evFork, 0);
    cudaStreamWaitEvent(s2, evFork, 0);

    // ---- CSR chain on side stream (independent of linear1) ----
    count_kernel<<<(N_EDGESC + 255) / 256, 256, 0, s2>>>(ei, ew);
    scan1_kernel<<<SCAN_GRID, SCAN_BLK, 0, s2>>>();
    scan3_kernel<<<SCAN_GRID, SCAN_BLK, 0, s2>>>();
    scatter_kernel<<<(E2C + 255) / 256, 256, 0, s2>>>(ei, ew);
    cudaEventRecord(evJoin, s2);

    // ---- linear1 on main stream, concurrent with the CSR chain ----
    linear_fused_kernel<D_INC, D_HIDC, 64, 32, 0><<<(N_NODESC + 63) / 64, 256>>>(
        x, Wl1, bl1, Wr1, br1, 0);

    // join: gat1 needs both linear1 (main) and scatter (side)
    cudaStreamWaitEvent(0, evJoin, 0);
    gat_node_kernel<D_HIDC, 0><<<GRID_GAT, 256>>>(We1, att1, bias1, out);

    // ---- layer 2 (serial dependencies) ----
    linear_fused_kernel<D_HIDC, D_OUTC, 128, 32, 1><<<(N_NODESC + 127) / 128, 256>>>(
        x, Wl2, bl2, Wr2, br2, 1);
    gat_node_kernel<D_OUTC, 1><<<GRID_GAT, 256>>>(We2, att2, bias2, out);
}